// round 2
// baseline (speedup 1.0000x reference)
#include <cuda_runtime.h>
#include <math.h>

#define Nn 40000
#define Ee 320000
#define Dd 128
#define Hh 4
#define DK 32
#define Tt 3
#define Rr 5
#define Kk 3
#define ND 5120000      // N*D
#define EH 1280000      // E*H
#define NH 160000       // N*H
#define RELF 20480      // R*H*DK*DK floats

// ---------------- device scratch (static globals: allocation-free) ----------
__device__ __align__(16) float g_qn[ND];
__device__ __align__(16) float g_kn[ND];
__device__ __align__(16) float g_vn[ND];
__device__ __align__(16) float g_ex[EH];     // logits, then exp values
__device__ __align__(16) float g_mx[NH];
__device__ __align__(16) float g_den[NH];
__device__ int   g_deg[Nn];
__device__ int   g_perm[Nn];
__device__ int   g_tcount[Tt];
__device__ int   g_toff[Tt + 1];
__device__ int   g_cursor[Tt];
__device__ __align__(16) float g_agg[Kk * ND];    // agg with root applied
__device__ __align__(16) float g_aggm[Kk * ND];
__device__ __align__(16) float g_qlin[ND];
__device__ __align__(16) float g_front[Kk * ND];
__device__ __align__(16) float g_tail[Kk * ND];
__device__ __align__(16) float g_hbuf[ND];
__device__ __align__(16) float g_trans[ND];

// ---------------- helpers ----------------
__device__ __forceinline__ float sigmoidf_(float x) { return 1.0f / (1.0f + expf(-x)); }

__device__ __forceinline__ void atomicMaxF(float* addr, float v) {
    int old = __float_as_int(*addr);
    while (__int_as_float(old) < v) {
        int prev = atomicCAS((int*)addr, old, __float_as_int(v));
        if (prev == old) break;
        old = prev;
    }
}

// ---------------- setup kernels ----------------
__global__ void k_init() {
    int tid = blockIdx.x * 256 + threadIdx.x;
    if (tid < NH) { g_mx[tid] = __int_as_float(0xff800000); g_den[tid] = 0.0f; }
    if (tid < Nn) g_deg[tid] = 0;
    if (tid < Tt) { g_tcount[tid] = 0; g_cursor[tid] = 0; }
}

__global__ void k_count(const int* __restrict__ node_type, const int* __restrict__ ei) {
    int tid = blockIdx.x * 256 + threadIdx.x;
    if (tid < Nn) atomicAdd(&g_tcount[node_type[tid]], 1);
    if (tid < Ee) atomicAdd(&g_deg[ei[Ee + tid]], 1);
}

__global__ void k_scan() {
    if (threadIdx.x == 0 && blockIdx.x == 0) {
        g_toff[0] = 0;
        for (int t = 0; t < Tt; t++) g_toff[t + 1] = g_toff[t] + g_tcount[t];
    }
}

__global__ void k_scatter(const int* __restrict__ node_type) {
    int tid = blockIdx.x * 256 + threadIdx.x;
    if (tid < Nn) {
        int t = node_type[tid];
        int pos = g_toff[t] + atomicAdd(&g_cursor[t], 1);
        g_perm[pos] = tid;
    }
}

// ---------------- GEMM: C[rows,128] = A[rows,128] @ B[128,128] (+ bias) ------
// 64-row tile, 256 threads, 4x8 micro-tile per thread, K chunked by 32.

__global__ void __launch_bounds__(256) k_gemm(
    const float* __restrict__ Ab, long long sA,
    const float* __restrict__ Bb, long long sB,
    const float* __restrict__ biasb, long long sBias,
    float* __restrict__ Cb, long long sC, int M)
{
    const float* A = Ab + (long long)blockIdx.z * sA;
    const float* B = Bb + (long long)blockIdx.z * sB;
    const float* bias = biasb ? (biasb + (long long)blockIdx.z * sBias) : nullptr;
    float* C = Cb + (long long)blockIdx.z * sC;
    int row0 = blockIdx.x * 64;
    if (row0 >= M) return;

    __shared__ float Bs[32][132];
    __shared__ float AsT[32][68];
    int tid = threadIdx.x;
    int tc = tid & 15, tr = tid >> 4;

    float acc[4][8];
#pragma unroll
    for (int i = 0; i < 4; i++)
#pragma unroll
        for (int j = 0; j < 8; j++) acc[i][j] = 0.0f;

#pragma unroll 1
    for (int kc = 0; kc < 4; kc++) {
        __syncthreads();
#pragma unroll
        for (int j = 0; j < 4; j++) {
            int id = tid + 256 * j;
            int brow = id >> 5, bc = id & 31;
            *(float4*)&Bs[brow][bc * 4] =
                *(const float4*)&B[(kc * 32 + brow) * 128 + bc * 4];
        }
#pragma unroll
        for (int j = 0; j < 2; j++) {
            int id = tid + 256 * j;
            int arow = id >> 3, a4 = id & 7;
            int grow = row0 + arow;
            float4 v = make_float4(0.f, 0.f, 0.f, 0.f);
            if (grow < M) v = *(const float4*)&A[(long long)grow * 128 + kc * 32 + a4 * 4];
            AsT[a4 * 4 + 0][arow] = v.x;
            AsT[a4 * 4 + 1][arow] = v.y;
            AsT[a4 * 4 + 2][arow] = v.z;
            AsT[a4 * 4 + 3][arow] = v.w;
        }
        __syncthreads();
#pragma unroll
        for (int k = 0; k < 32; k++) {
            const float4 av = *(const float4*)&AsT[k][tr * 4];
            const float4 b0 = *(const float4*)&Bs[k][tc * 8];
            const float4 b1 = *(const float4*)&Bs[k][tc * 8 + 4];
            float aa[4] = {av.x, av.y, av.z, av.w};
            float bb[8] = {b0.x, b0.y, b0.z, b0.w, b1.x, b1.y, b1.z, b1.w};
#pragma unroll
            for (int i = 0; i < 4; i++)
#pragma unroll
                for (int j = 0; j < 8; j++)
                    acc[i][j] = fmaf(aa[i], bb[j], acc[i][j]);
        }
    }

#pragma unroll
    for (int i = 0; i < 4; i++) {
        int grow = row0 + tr * 4 + i;
        if (grow < M) {
#pragma unroll
            for (int jb = 0; jb < 8; jb += 4) {
                float4 o;
                float b0 = bias ? bias[tc * 8 + jb + 0] : 0.0f;
                float b1 = bias ? bias[tc * 8 + jb + 1] : 0.0f;
                float b2 = bias ? bias[tc * 8 + jb + 2] : 0.0f;
                float b3 = bias ? bias[tc * 8 + jb + 3] : 0.0f;
                o.x = acc[i][jb + 0] + b0;
                o.y = acc[i][jb + 1] + b1;
                o.z = acc[i][jb + 2] + b2;
                o.w = acc[i][jb + 3] + b3;
                *(float4*)&C[(long long)grow * 128 + tc * 8 + jb] = o;
            }
        }
    }
}

// Typed GEMM: rows bucketed by node type via g_perm; W/bias selected by blockIdx.y
__global__ void __launch_bounds__(256) k_typed_gemm(
    const float* __restrict__ A, const float* __restrict__ W,
    const float* __restrict__ bias, float* __restrict__ C)
{
    int ty = blockIdx.y;
    int bstart = g_toff[ty], bend = g_toff[ty + 1];
    int row0 = bstart + (int)blockIdx.x * 64;
    if (row0 >= bend) return;
    const float* B = W + ty * 16384;
    const float* bi = bias + ty * 128;

    __shared__ float Bs[32][132];
    __shared__ float AsT[32][68];
    int tid = threadIdx.x;
    int tc = tid & 15, tr = tid >> 4;

    float acc[4][8];
#pragma unroll
    for (int i = 0; i < 4; i++)
#pragma unroll
        for (int j = 0; j < 8; j++) acc[i][j] = 0.0f;

#pragma unroll 1
    for (int kc = 0; kc < 4; kc++) {
        __syncthreads();
#pragma unroll
        for (int j = 0; j < 4; j++) {
            int id = tid + 256 * j;
            int brow = id >> 5, bc = id & 31;
            *(float4*)&Bs[brow][bc * 4] =
                *(const float4*)&B[(kc * 32 + brow) * 128 + bc * 4];
        }
#pragma unroll
        for (int j = 0; j < 2; j++) {
            int id = tid + 256 * j;
            int arow = id >> 3, a4 = id & 7;
            int grow = row0 + arow;
            float4 v = make_float4(0.f, 0.f, 0.f, 0.f);
            if (grow < bend) {
                int node = g_perm[grow];
                v = *(const float4*)&A[(long long)node * 128 + kc * 32 + a4 * 4];
            }
            AsT[a4 * 4 + 0][arow] = v.x;
            AsT[a4 * 4 + 1][arow] = v.y;
            AsT[a4 * 4 + 2][arow] = v.z;
            AsT[a4 * 4 + 3][arow] = v.w;
        }
        __syncthreads();
#pragma unroll
        for (int k = 0; k < 32; k++) {
            const float4 av = *(const float4*)&AsT[k][tr * 4];
            const float4 b0 = *(const float4*)&Bs[k][tc * 8];
            const float4 b1 = *(const float4*)&Bs[k][tc * 8 + 4];
            float aa[4] = {av.x, av.y, av.z, av.w};
            float bb[8] = {b0.x, b0.y, b0.z, b0.w, b1.x, b1.y, b1.z, b1.w};
#pragma unroll
            for (int i = 0; i < 4; i++)
#pragma unroll
                for (int j = 0; j < 8; j++)
                    acc[i][j] = fmaf(aa[i], bb[j], acc[i][j]);
        }
    }

#pragma unroll
    for (int i = 0; i < 4; i++) {
        int grow = row0 + tr * 4 + i;
        if (grow < bend) {
            int node = g_perm[grow];
#pragma unroll
            for (int jb = 0; jb < 8; jb += 4) {
                float4 o;
                o.x = acc[i][jb + 0] + bi[tc * 8 + jb + 0];
                o.y = acc[i][jb + 1] + bi[tc * 8 + jb + 1];
                o.z = acc[i][jb + 2] + bi[tc * 8 + jb + 2];
                o.w = acc[i][jb + 3] + bi[tc * 8 + jb + 3];
                *(float4*)&C[(long long)node * 128 + tc * 8 + jb] = o;
            }
        }
    }
}

// ---------------- edge stage: logits + segment max -------------------------
// persistent blocks, rel_att resident in dynamic smem (80 KB)
__global__ void __launch_bounds__(256) k_edge(
    const int* __restrict__ ei, const int* __restrict__ et,
    const float* __restrict__ rel_att, const float* __restrict__ rel_pri)
{
    extern __shared__ float sh[];
    float* relS = sh;            // RELF floats
    float* keS = sh + RELF;      // 8 * 128
    for (int i = threadIdx.x; i < RELF; i += 256) relS[i] = rel_att[i];
    __syncthreads();

    int warp = threadIdx.x >> 5, lane = threadIdx.x & 31;
    float* keW = keS + warp * 128;
    int stride = gridDim.x * 8;
    for (int e = blockIdx.x * 8 + warp; e < Ee; e += stride) {
        int s = ei[e], t = ei[Ee + e], r = et[e];
        __syncwarp();
#pragma unroll
        for (int h = 0; h < 4; h++)
            keW[h * 32 + lane] = g_kn[(long long)s * 128 + h * 32 + lane];
        __syncwarp();
#pragma unroll
        for (int h = 0; h < 4; h++) {
            const float* Am = relS + (r * 4 + h) * 1024;
            float a0 = 0.f, a1 = 0.f;
#pragma unroll
            for (int d = 0; d < 32; d += 2) {
                a0 = fmaf(keW[h * 32 + d],     Am[d * 32 + lane],       a0);
                a1 = fmaf(keW[h * 32 + d + 1], Am[(d + 1) * 32 + lane], a1);
            }
            float kp = a0 + a1;
            float p = g_qn[(long long)t * 128 + h * 32 + lane] * kp;
#pragma unroll
            for (int o = 16; o > 0; o >>= 1) p += __shfl_xor_sync(0xffffffffu, p, o);
            if (lane == 0) {
                float lg = p * rel_pri[r * 4 + h] * 0.17677669529663687f;
                g_ex[e * 4 + h] = lg;
                atomicMaxF(&g_mx[t * 4 + h], lg);
            }
        }
    }
}

// ---------------- exp + denominator ----------------------------------------
__global__ void k_expden(const int* __restrict__ ei) {
    int tid = blockIdx.x * 256 + threadIdx.x;
    if (tid >= EH) return;
    int e = tid >> 2, h = tid & 3;
    int t = ei[Ee + e];
    float v = expf(g_ex[tid] - g_mx[t * 4 + h]);
    g_ex[tid] = v;
    atomicAdd(&g_den[t * 4 + h], v);
}

// ---------------- messages / aggregation (only edge ids < N matter!) --------
__global__ void __launch_bounds__(256) k_msg(
    const int* __restrict__ ei, const int* __restrict__ et,
    const float* __restrict__ rel_msg)
{
    extern __shared__ float sh[];
    float* relS = sh;
    float* vnS = sh + RELF;
    for (int i = threadIdx.x; i < RELF; i += 256) relS[i] = rel_msg[i];
    __syncthreads();

    int warp = threadIdx.x >> 5, lane = threadIdx.x & 31;
    float* vW = vnS + warp * 128;
    int stride = gridDim.x * 8;
    for (int n = blockIdx.x * 8 + warp; n < Nn; n += stride) {
        int s = ei[n], t = ei[Ee + n], r = et[n];
        __syncwarp();
#pragma unroll
        for (int h = 0; h < 4; h++)
            vW[h * 32 + lane] = g_vn[(long long)s * 128 + h * 32 + lane];
        __syncwarp();
        float deg = (float)g_deg[n];
#pragma unroll
        for (int h = 0; h < 4; h++) {
            float att = g_ex[n * 4 + h] / (g_den[t * 4 + h] + 1e-16f);
            const float* Am = relS + (r * 4 + h) * 1024;
            float a0 = 0.f, a1 = 0.f;
#pragma unroll
            for (int d = 0; d < 32; d += 2) {
                a0 = fmaf(vW[h * 32 + d],     Am[d * 32 + lane],       a0);
                a1 = fmaf(vW[h * 32 + d + 1], Am[(d + 1) * 32 + lane], a1);
            }
            float vp = a0 + a1;
            float c = att * deg;
            long long o = (long long)n * 128 + h * 32 + lane;
            float m1 = vp * c;
            float m2 = vp * vp * c;
            float m3 = vp * vp * vp * c;
            float s3 = (m3 > 0.f) ? 1.f : ((m3 < 0.f) ? -1.f : 0.f);
            float r3 = s3 * powf(fabsf(m3) + 1e-18f, 0.33333333333333333f);
            g_agg[o] = m1;
            g_agg[ND + o] = m2;
            g_agg[2 * ND + o] = r3;
        }
    }
}

// ---------------- gating + residual moments + gelu --------------------------
__global__ void __launch_bounds__(256) k_res() {
    int warp = threadIdx.x >> 5, lane = threadIdx.x & 31;
    int n = blockIdx.x * 8 + warp;
    if (n >= Nn) return;
    long long base = (long long)n * 128 + lane * 4;
    float r0 = 0.f, r1 = 0.f, r2 = 0.f, r3 = 0.f;
#pragma unroll
    for (int kk = 0; kk < 3; kk++) {
        const float4 f = *(const float4*)&g_front[kk * ND + base];
        const float4 t4 = *(const float4*)&g_tail[kk * ND + base];
        float p = f.x * t4.x + f.y * t4.y + f.z * t4.z + f.w * t4.w;
#pragma unroll
        for (int o = 16; o > 0; o >>= 1) p += __shfl_xor_sync(0xffffffffu, p, o);
        float tt = sigmoidf_(p);
        const float4 am = *(const float4*)&g_aggm[kk * ND + base];
        r0 = fmaf(tt, am.x, r0);
        r1 = fmaf(tt, am.y, r1);
        r2 = fmaf(tt, am.z, r2);
        r3 = fmaf(tt, am.w, r3);
    }
    float4 o;
    o.x = 0.5f * r0 * (1.0f + erff(r0 * 0.70710678118654752f));
    o.y = 0.5f * r1 * (1.0f + erff(r1 * 0.70710678118654752f));
    o.z = 0.5f * r2 * (1.0f + erff(r2 * 0.70710678118654752f));
    o.w = 0.5f * r3 * (1.0f + erff(r3 * 0.70710678118654752f));
    *(float4*)&g_hbuf[base] = o;
}

// ---------------- skip-mix + per-type LayerNorm -----------------------------
__global__ void __launch_bounds__(256) k_final(
    const float* __restrict__ meta, const int* __restrict__ node_type,
    const float* __restrict__ skip, const float* __restrict__ ln_g,
    const float* __restrict__ ln_b, float* __restrict__ out)
{
    int warp = threadIdx.x >> 5, lane = threadIdx.x & 31;
    int n = blockIdx.x * 8 + warp;
    if (n >= Nn) return;
    int t = node_type[n];
    float alpha = sigmoidf_(skip[t]);
    long long base = (long long)n * 128 + lane * 4;
    const float4 tr = *(const float4*)&g_trans[base];
    const float4 x = *(const float4*)&meta[base];
    float y0 = tr.x * alpha + x.x * (1.0f - alpha);
    float y1 = tr.y * alpha + x.y * (1.0f - alpha);
    float y2 = tr.z * alpha + x.z * (1.0f - alpha);
    float y3 = tr.w * alpha + x.w * (1.0f - alpha);
    float s = y0 + y1 + y2 + y3;
    float sq = y0 * y0 + y1 * y1 + y2 * y2 + y3 * y3;
#pragma unroll
    for (int o = 16; o > 0; o >>= 1) {
        s += __shfl_xor_sync(0xffffffffu, s, o);
        sq += __shfl_xor_sync(0xffffffffu, sq, o);
    }
    float mu = s * (1.0f / 128.0f);
    float var = sq * (1.0f / 128.0f) - mu * mu;
    float inv = 1.0f / sqrtf(var + 1e-5f);
    int c = lane * 4;
    const float4 g = *(const float4*)&ln_g[t * 128 + c];
    const float4 b = *(const float4*)&ln_b[t * 128 + c];
    float4 o;
    o.x = (y0 - mu) * inv * g.x + b.x;
    o.y = (y1 - mu) * inv * g.y + b.y;
    o.z = (y2 - mu) * inv * g.z + b.z;
    o.w = (y3 - mu) * inv * g.w + b.w;
    *(float4*)&out[base] = o;
}

// ---------------- host launcher ---------------------------------------------
extern "C" void kernel_launch(void* const* d_in, const int* in_sizes, int n_in,
                              void* d_out, int out_size)
{
    const float* meta      = (const float*)d_in[0];
    const int*   node_type = (const int*)d_in[1];
    const int*   ei        = (const int*)d_in[2];
    const int*   etype     = (const int*)d_in[3];
    // d_in[4] = edge_time (unused)
    const float* q_w = (const float*)d_in[5];
    const float* q_b = (const float*)d_in[6];
    const float* k_w = (const float*)d_in[7];
    const float* k_b = (const float*)d_in[8];
    const float* v_w = (const float*)d_in[9];
    const float* v_b = (const float*)d_in[10];
    const float* a_w = (const float*)d_in[11];
    const float* a_b = (const float*)d_in[12];
    const float* rel_pri = (const float*)d_in[13];
    const float* rel_att = (const float*)d_in[14];
    const float* rel_msg = (const float*)d_in[15];
    const float* WMk = (const float*)d_in[16];
    const float* Wak = (const float*)d_in[17];
    const float* Wq  = (const float*)d_in[18];
    const float* bq  = (const float*)d_in[19];
    const float* Wkl = (const float*)d_in[20];
    const float* bkl = (const float*)d_in[21];
    const float* skip = (const float*)d_in[22];
    const float* ln_g = (const float*)d_in[23];
    const float* ln_b = (const float*)d_in[24];
    float* out = (float*)d_out;

    float *p_qn, *p_kn, *p_vn, *p_qlin, *p_agg, *p_aggm, *p_front, *p_tail, *p_hbuf, *p_trans;
    cudaGetSymbolAddress((void**)&p_qn, g_qn);
    cudaGetSymbolAddress((void**)&p_kn, g_kn);
    cudaGetSymbolAddress((void**)&p_vn, g_vn);
    cudaGetSymbolAddress((void**)&p_qlin, g_qlin);
    cudaGetSymbolAddress((void**)&p_agg, g_agg);
    cudaGetSymbolAddress((void**)&p_aggm, g_aggm);
    cudaGetSymbolAddress((void**)&p_front, g_front);
    cudaGetSymbolAddress((void**)&p_tail, g_tail);
    cudaGetSymbolAddress((void**)&p_hbuf, g_hbuf);
    cudaGetSymbolAddress((void**)&p_trans, g_trans);

    const int SMEM_EDGE = (RELF + 8 * 128) * 4;  // 86016 B
    cudaFuncSetAttribute(k_edge, cudaFuncAttributeMaxDynamicSharedMemorySize, SMEM_EDGE);
    cudaFuncSetAttribute(k_msg,  cudaFuncAttributeMaxDynamicSharedMemorySize, SMEM_EDGE);

    dim3 blk(256);

    k_init<<<625, blk>>>();
    k_count<<<1250, blk>>>(node_type, ei);
    k_scan<<<1, 32>>>();
    k_scatter<<<157, blk>>>(node_type);

    // typed q/k/v projections
    k_typed_gemm<<<dim3(625, 3, 1), blk>>>(meta, q_w, q_b, p_qn);
    k_typed_gemm<<<dim3(625, 3, 1), blk>>>(meta, k_w, k_b, p_kn);
    k_typed_gemm<<<dim3(625, 3, 1), blk>>>(meta, v_w, v_b, p_vn);

    // qlin = meta @ Wq + bq (independent)
    k_gemm<<<dim3(625, 1, 1), blk>>>(meta, 0, Wq, 0, bq, 0, p_qlin, 0, Nn);

    // attention logits + segment max, then exp + denominators
    k_edge<<<296, blk, SMEM_EDGE>>>(ei, etype, rel_att, rel_pri);
    k_expden<<<5000, blk>>>(ei);

    // messages for edge ids < N, aggregated via degree (reference quirk)
    k_msg<<<296, blk, SMEM_EDGE>>>(ei, etype, rel_msg);

    // aggm[k] = agg[k] @ WMk[k]
    k_gemm<<<dim3(625, 1, 3), blk>>>(p_agg, ND, WMk, 16384, nullptr, 0, p_aggm, ND, Nn);
    // front[k] = qlin @ Wak[k]
    k_gemm<<<dim3(625, 1, 3), blk>>>(p_qlin, 0, Wak, 16384, nullptr, 0, p_front, ND, Nn);
    // tail[k] = aggm[k] @ Wkl + bkl
    k_gemm<<<dim3(625, 1, 3), blk>>>(p_aggm, ND, Wkl, 0, bkl, 0, p_tail, ND, Nn);

    // gating + residual + gelu
    k_res<<<5000, blk>>>();

    // trans = typed(gelu(res), a_w, a_b)
    k_typed_gemm<<<dim3(625, 3, 1), blk>>>(p_hbuf, a_w, a_b, p_trans);

    // skip-mix + per-type LayerNorm -> output
    k_final<<<5000, blk>>>(meta, node_type, skip, ln_g, ln_b, out);
}

// round 3
// speedup vs baseline: 1.8184x; 1.8184x over previous
#include <cuda_runtime.h>
#include <math.h>

#define Nn 40000
#define Ee 320000
#define Dd 128
#define Hh 4
#define DK 32
#define Tt 3
#define Rr 5
#define Kk 3
#define ND 5120000      // N*D
#define EH 1280000      // E*H
#define NH 160000       // N*H
#define RELF 20480      // R*H*DK*DK floats

typedef unsigned long long ull;

// ---------------- device scratch ----------------
__device__ __align__(16) float g_qn[ND];
__device__ __align__(16) float g_kn[ND];
__device__ __align__(16) float g_vn[ND];
__device__ __align__(16) float g_knr[Rr * ND];   // [r][n][128]
__device__ __align__(16) float g_ex[EH];
__device__ __align__(16) float g_mx[NH];
__device__ __align__(16) float g_den[NH];
__device__ int   g_deg[Nn];
__device__ int   g_perm[Nn];
__device__ int   g_tcount[Tt];
__device__ int   g_toff[Tt + 1];
__device__ int   g_cursor[Tt];
__device__ __align__(16) float g_agg[Kk * ND];
__device__ __align__(16) float g_aggm[Kk * ND];
__device__ __align__(16) float g_front[Kk * ND];
__device__ __align__(16) float g_tail[Kk * ND];
__device__ __align__(16) float g_hbuf[ND];
__device__ __align__(16) float g_trans[ND];
__device__ __align__(16) float g_wcomb[Kk * 16384];
__device__ __align__(16) float g_bfront[Kk * 128];

// ---------------- helpers ----------------
__device__ __forceinline__ float sigmoidf_(float x) { return 1.0f / (1.0f + expf(-x)); }

__device__ __forceinline__ void atomicMaxF(float* addr, float v) {
    int old = __float_as_int(*addr);
    while (__int_as_float(old) < v) {
        int prev = atomicCAS((int*)addr, old, __float_as_int(v));
        if (prev == old) break;
        old = prev;
    }
}

__device__ __forceinline__ void fma2(ull& d, ull a, ull b) {
    asm("fma.rn.f32x2 %0, %1, %2, %0;" : "+l"(d) : "l"(a), "l"(b));
}
__device__ __forceinline__ ull dup2(float x) {
    ull r; asm("mov.b64 %0, {%1, %1};" : "=l"(r) : "f"(x)); return r;
}
__device__ __forceinline__ ull pack2(float x, float y) {
    ull r; asm("mov.b64 %0, {%1, %2};" : "=l"(r) : "f"(x), "f"(y)); return r;
}
__device__ __forceinline__ float2 unpack2(ull v) {
    float2 f; asm("mov.b64 {%0, %1}, %2;" : "=f"(f.x), "=f"(f.y) : "l"(v)); return f;
}

// ---------------- setup ----------------
__global__ void k_init() {
    int tid = blockIdx.x * 256 + threadIdx.x;
    if (tid < NH) { g_mx[tid] = __int_as_float(0xff800000); g_den[tid] = 0.0f; }
    if (tid < Nn) g_deg[tid] = 0;
    if (tid < Tt) { g_tcount[tid] = 0; g_cursor[tid] = 0; }
}
__global__ void k_count(const int* __restrict__ node_type, const int* __restrict__ ei) {
    int tid = blockIdx.x * 256 + threadIdx.x;
    if (tid < Nn) atomicAdd(&g_tcount[node_type[tid]], 1);
    if (tid < Ee) atomicAdd(&g_deg[ei[Ee + tid]], 1);
}
__global__ void k_scan() {
    if (threadIdx.x == 0 && blockIdx.x == 0) {
        g_toff[0] = 0;
        for (int t = 0; t < Tt; t++) g_toff[t + 1] = g_toff[t] + g_tcount[t];
    }
}
__global__ void k_scatter(const int* __restrict__ node_type) {
    int tid = blockIdx.x * 256 + threadIdx.x;
    if (tid < Nn) {
        int t = node_type[tid];
        int pos = g_toff[t] + atomicAdd(&g_cursor[t], 1);
        g_perm[pos] = tid;
    }
}

// ============ FFMA2 GEMM core macros ============
// tile 128x128, 256 threads, microtile 4 rows x 16 cols, pairs over cols.
// Bs swizzle: Bs[k][(bc&3)*32 + (bc>>2)*4 + c] = B[k][bc*4+c]
// compute:    float4 at Bs[k][j4*32 + tc*4] = cols tc*16 + j4*4 .. +3

#define GEMM_INNER(AS, BS)                                                   \
    _Pragma("unroll")                                                        \
    for (int k = 0; k < 32; k++) {                                           \
        const float4 av = *(const float4*)&AS;                               \
        ull a0 = dup2(av.x), a1 = dup2(av.y), a2 = dup2(av.z), a3 = dup2(av.w); \
        _Pragma("unroll")                                                    \
        for (int j4 = 0; j4 < 4; j4++) {                                     \
            const float4 bv = *(const float4*)&BS;                           \
            ull b0 = pack2(bv.x, bv.y), b1 = pack2(bv.z, bv.w);              \
            fma2(acc[0][2*j4], a0, b0); fma2(acc[0][2*j4+1], a0, b1);        \
            fma2(acc[1][2*j4], a1, b0); fma2(acc[1][2*j4+1], a1, b1);        \
            fma2(acc[2][2*j4], a2, b0); fma2(acc[2][2*j4+1], a2, b1);        \
            fma2(acc[3][2*j4], a3, b0); fma2(acc[3][2*j4+1], a3, b1);        \
        }                                                                    \
    }

// ---------------- dense GEMM: C[M,128] = A[M,128] @ B[128,128] (+bias) ------
__global__ void __launch_bounds__(256) k_gemm2(
    const float* __restrict__ Ab, long long sA,
    const float* __restrict__ Bb, long long sB,
    const float* __restrict__ biasb, long long sBias,
    float* __restrict__ Cb, long long sC, int M)
{
    const float* A = Ab + (long long)blockIdx.z * sA;
    const float* B = Bb + (long long)blockIdx.z * sB;
    const float* bias = biasb ? (biasb + (long long)blockIdx.z * sBias) : nullptr;
    float* C = Cb + (long long)blockIdx.z * sC;
    int row0 = blockIdx.x * 128;
    if (row0 >= M) return;

    __shared__ float Bs[32][132];
    __shared__ float AsT[32][132];
    int tid = threadIdx.x;
    int tr = tid >> 3, tc = tid & 7;

    ull acc[4][8];
#pragma unroll
    for (int i = 0; i < 4; i++)
#pragma unroll
        for (int j = 0; j < 8; j++) acc[i][j] = 0ULL;

#pragma unroll 1
    for (int kc = 0; kc < 4; kc++) {
        __syncthreads();
#pragma unroll
        for (int j = 0; j < 4; j++) {
            int id = tid + 256 * j;
            int brow = id >> 5, bc = id & 31;
            float4 v = *(const float4*)&B[(kc * 32 + brow) * 128 + bc * 4];
            *(float4*)&Bs[brow][(bc & 3) * 32 + (bc >> 2) * 4] = v;
        }
#pragma unroll
        for (int j = 0; j < 4; j++) {
            int id = tid + 256 * j;
            int arow = id >> 3, a4 = id & 7;
            int grow = row0 + arow;
            float4 v = make_float4(0.f, 0.f, 0.f, 0.f);
            if (grow < M) v = *(const float4*)&A[(long long)grow * 128 + kc * 32 + a4 * 4];
            AsT[a4 * 4 + 0][arow] = v.x;
            AsT[a4 * 4 + 1][arow] = v.y;
            AsT[a4 * 4 + 2][arow] = v.z;
            AsT[a4 * 4 + 3][arow] = v.w;
        }
        __syncthreads();
        GEMM_INNER(AsT[k][tr * 4], Bs[k][j4 * 32 + tc * 4])
    }

#pragma unroll
    for (int i = 0; i < 4; i++) {
        int grow = row0 + tr * 4 + i;
        if (grow < M) {
#pragma unroll
            for (int j4 = 0; j4 < 4; j4++) {
                float2 u0 = unpack2(acc[i][2 * j4]);
                float2 u1 = unpack2(acc[i][2 * j4 + 1]);
                int col = tc * 16 + j4 * 4;
                float4 o = make_float4(u0.x, u0.y, u1.x, u1.y);
                if (bias) {
                    o.x += bias[col]; o.y += bias[col + 1];
                    o.z += bias[col + 2]; o.w += bias[col + 3];
                }
                *(float4*)&C[(long long)grow * 128 + col] = o;
            }
        }
    }
}

// ---------------- typed GEMM via g_perm -------------------------------------
__global__ void __launch_bounds__(256) k_typed_gemm2(
    const float* __restrict__ A, const float* __restrict__ W,
    const float* __restrict__ biasT, float* __restrict__ C)
{
    int ty = blockIdx.y;
    int bstart = g_toff[ty], bend = g_toff[ty + 1];
    int row0 = bstart + (int)blockIdx.x * 128;
    if (row0 >= bend) return;
    const float* B = W + ty * 16384;
    const float* bias = biasT + ty * 128;

    __shared__ float Bs[32][132];
    __shared__ float AsT[32][132];
    __shared__ int rowmap[128];
    int tid = threadIdx.x;
    int tr = tid >> 3, tc = tid & 7;

    if (tid < 128) {
        int grow = row0 + tid;
        rowmap[tid] = (grow < bend) ? g_perm[grow] : -1;
    }

    ull acc[4][8];
#pragma unroll
    for (int i = 0; i < 4; i++)
#pragma unroll
        for (int j = 0; j < 8; j++) acc[i][j] = 0ULL;

#pragma unroll 1
    for (int kc = 0; kc < 4; kc++) {
        __syncthreads();
#pragma unroll
        for (int j = 0; j < 4; j++) {
            int id = tid + 256 * j;
            int brow = id >> 5, bc = id & 31;
            float4 v = *(const float4*)&B[(kc * 32 + brow) * 128 + bc * 4];
            *(float4*)&Bs[brow][(bc & 3) * 32 + (bc >> 2) * 4] = v;
        }
#pragma unroll
        for (int j = 0; j < 4; j++) {
            int id = tid + 256 * j;
            int arow = id >> 3, a4 = id & 7;
            int node = rowmap[arow];
            float4 v = make_float4(0.f, 0.f, 0.f, 0.f);
            if (node >= 0) v = *(const float4*)&A[(long long)node * 128 + kc * 32 + a4 * 4];
            AsT[a4 * 4 + 0][arow] = v.x;
            AsT[a4 * 4 + 1][arow] = v.y;
            AsT[a4 * 4 + 2][arow] = v.z;
            AsT[a4 * 4 + 3][arow] = v.w;
        }
        __syncthreads();
        GEMM_INNER(AsT[k][tr * 4], Bs[k][j4 * 32 + tc * 4])
    }

#pragma unroll
    for (int i = 0; i < 4; i++) {
        int node = rowmap[tr * 4 + i];
        if (node >= 0) {
#pragma unroll
            for (int j4 = 0; j4 < 4; j4++) {
                float2 u0 = unpack2(acc[i][2 * j4]);
                float2 u1 = unpack2(acc[i][2 * j4 + 1]);
                int col = tc * 16 + j4 * 4;
                float4 o = make_float4(u0.x + bias[col], u0.y + bias[col + 1],
                                       u1.x + bias[col + 2], u1.y + bias[col + 3]);
                *(float4*)&C[(long long)node * 128 + col] = o;
            }
        }
    }
}

// ---------------- knr[r][n] = kn[n] block-diag rel_att[r] -------------------
// per-thread cols span one head (tc>>1); K loop only over the head's 32 dims.
__global__ void __launch_bounds__(256) k_rel_transform(const float* __restrict__ rel_att)
{
    extern __shared__ float sh[];
    float* AsT = sh;                  // [128][132]
    float* relSw = sh + 128 * 132;    // [32][132] swizzled
    int r = blockIdx.y;
    int row0 = blockIdx.x * 128;
    int tid = threadIdx.x;
    int tr = tid >> 3, tc = tid & 7, h = tc >> 1;

    // stage rel_att[r] swizzled: col = tc*16 + j4*4 + c; h=tc>>1; cin=(tc&1)*16+j4*4+c
#pragma unroll
    for (int j = 0; j < 16; j++) {
        int idx = tid + 256 * j;
        int hh = idx >> 10, d = (idx >> 5) & 31, cin = idx & 31;
        int off = ((cin >> 2) & 3) * 32 + (hh * 2 + (cin >> 4)) * 4 + (cin & 3);
        relSw[d * 132 + off] = rel_att[r * 4096 + idx];
    }
    // stage A (kn rows) transposed
#pragma unroll
    for (int j = 0; j < 16; j++) {
        int id = tid + 256 * j;
        int arow = id >> 5, af = id & 31;
        int grow = row0 + arow;
        float4 v = make_float4(0.f, 0.f, 0.f, 0.f);
        if (grow < Nn) v = *(const float4*)&g_kn[(long long)grow * 128 + af * 4];
        AsT[(af * 4 + 0) * 132 + arow] = v.x;
        AsT[(af * 4 + 1) * 132 + arow] = v.y;
        AsT[(af * 4 + 2) * 132 + arow] = v.z;
        AsT[(af * 4 + 3) * 132 + arow] = v.w;
    }
    __syncthreads();

    ull acc[4][8];
#pragma unroll
    for (int i = 0; i < 4; i++)
#pragma unroll
        for (int j = 0; j < 8; j++) acc[i][j] = 0ULL;

#pragma unroll
    for (int k = 0; k < 32; k++) {
        const float4 av = *(const float4*)&AsT[((h << 5) + k) * 132 + tr * 4];
        ull a0 = dup2(av.x), a1 = dup2(av.y), a2 = dup2(av.z), a3 = dup2(av.w);
#pragma unroll
        for (int j4 = 0; j4 < 4; j4++) {
            const float4 bv = *(const float4*)&relSw[k * 132 + j4 * 32 + tc * 4];
            ull b0 = pack2(bv.x, bv.y), b1 = pack2(bv.z, bv.w);
            fma2(acc[0][2*j4], a0, b0); fma2(acc[0][2*j4+1], a0, b1);
            fma2(acc[1][2*j4], a1, b0); fma2(acc[1][2*j4+1], a1, b1);
            fma2(acc[2][2*j4], a2, b0); fma2(acc[2][2*j4+1], a2, b1);
            fma2(acc[3][2*j4], a3, b0); fma2(acc[3][2*j4+1], a3, b1);
        }
    }

    float* C = g_knr + (long long)r * ND;
#pragma unroll
    for (int i = 0; i < 4; i++) {
        int grow = row0 + tr * 4 + i;
        if (grow < Nn) {
#pragma unroll
            for (int j4 = 0; j4 < 4; j4++) {
                float2 u0 = unpack2(acc[i][2 * j4]);
                float2 u1 = unpack2(acc[i][2 * j4 + 1]);
                int col = tc * 16 + j4 * 4;
                *(float4*)&C[(long long)grow * 128 + col] =
                    make_float4(u0.x, u0.y, u1.x, u1.y);
            }
        }
    }
}

// ---------------- edge logits + segment max (coalesced dot) ------------------
__global__ void __launch_bounds__(256) k_logits(
    const int* __restrict__ ei, const int* __restrict__ et,
    const float* __restrict__ rel_pri)
{
    int warp = threadIdx.x >> 5, lane = threadIdx.x & 31;
    int w = blockIdx.x * 8 + warp;
    int stride = gridDim.x * 8;
    for (int e = w; e < Ee; e += stride) {
        int s = ei[e], t = ei[Ee + e], r = et[e];
        const float* q = g_qn + (long long)t * 128;
        const float* kk = g_knr + ((long long)r * Nn + s) * 128;
        float q0 = q[lane], q1 = q[32 + lane], q2 = q[64 + lane], q3 = q[96 + lane];
        float k0 = kk[lane], k1 = kk[32 + lane], k2 = kk[64 + lane], k3 = kk[96 + lane];
        float p0 = q0 * k0, p1 = q1 * k1, p2 = q2 * k2, p3 = q3 * k3;
#pragma unroll
        for (int o = 16; o > 0; o >>= 1) {
            p0 += __shfl_xor_sync(0xffffffffu, p0, o);
            p1 += __shfl_xor_sync(0xffffffffu, p1, o);
            p2 += __shfl_xor_sync(0xffffffffu, p2, o);
            p3 += __shfl_xor_sync(0xffffffffu, p3, o);
        }
        if (lane < 4) {
            float pv = (lane == 0) ? p0 : (lane == 1) ? p1 : (lane == 2) ? p2 : p3;
            float lg = pv * rel_pri[r * 4 + lane] * 0.17677669529663687f;
            g_ex[e * 4 + lane] = lg;
            atomicMaxF(&g_mx[t * 4 + lane], lg);
        }
    }
}

// ---------------- exp + denominator ----------------------------------------
__global__ void k_expden(const int* __restrict__ ei) {
    int tid = blockIdx.x * 256 + threadIdx.x;
    if (tid >= EH) return;
    int e = tid >> 2, h = tid & 3;
    int t = ei[Ee + e];
    float v = expf(g_ex[tid] - g_mx[t * 4 + h]);
    g_ex[tid] = v;
    atomicAdd(&g_den[t * 4 + h], v);
}

// ---------------- messages (only edge ids < N matter) -----------------------
__global__ void __launch_bounds__(256) k_msg(
    const int* __restrict__ ei, const int* __restrict__ et,
    const float* __restrict__ rel_msg)
{
    extern __shared__ float sh[];
    float* relS = sh;
    float* vnS = sh + RELF;
    for (int i = threadIdx.x; i < RELF; i += 256) relS[i] = rel_msg[i];
    __syncthreads();

    int warp = threadIdx.x >> 5, lane = threadIdx.x & 31;
    float* vW = vnS + warp * 128;
    int stride = gridDim.x * 8;
    for (int n = blockIdx.x * 8 + warp; n < Nn; n += stride) {
        int s = ei[n], t = ei[Ee + n], r = et[n];
        __syncwarp();
#pragma unroll
        for (int h = 0; h < 4; h++)
            vW[h * 32 + lane] = g_vn[(long long)s * 128 + h * 32 + lane];
        __syncwarp();
        float deg = (float)g_deg[n];
#pragma unroll
        for (int h = 0; h < 4; h++) {
            float att = g_ex[n * 4 + h] / (g_den[t * 4 + h] + 1e-16f);
            const float* Am = relS + (r * 4 + h) * 1024;
            float a0 = 0.f, a1 = 0.f;
#pragma unroll
            for (int d = 0; d < 32; d += 2) {
                a0 = fmaf(vW[h * 32 + d],     Am[d * 32 + lane],       a0);
                a1 = fmaf(vW[h * 32 + d + 1], Am[(d + 1) * 32 + lane], a1);
            }
            float vp = a0 + a1;
            float c = att * deg;
            long long o = (long long)n * 128 + h * 32 + lane;
            float m1 = vp * c;
            float m2 = vp * vp * c;
            float m3 = vp * vp * vp * c;
            float s3 = (m3 > 0.f) ? 1.f : ((m3 < 0.f) ? -1.f : 0.f);
            float r3 = s3 * powf(fabsf(m3) + 1e-18f, 0.33333333333333333f);
            g_agg[o] = m1;
            g_agg[ND + o] = m2;
            g_agg[2 * ND + o] = r3;
        }
    }
}

// ---------------- bfront[k] = bq @ Wak[k] -----------------------------------
__global__ void k_bfront(const float* __restrict__ Wak, const float* __restrict__ bq) {
    int kk = blockIdx.x, j = threadIdx.x;
    float s = 0.f;
#pragma unroll 4
    for (int d = 0; d < 128; d++)
        s = fmaf(bq[d], Wak[kk * 16384 + d * 128 + j], s);
    g_bfront[kk * 128 + j] = s;
}

// ---------------- gating + residual + gelu ----------------------------------
__global__ void __launch_bounds__(256) k_res() {
    int warp = threadIdx.x >> 5, lane = threadIdx.x & 31;
    int n = blockIdx.x * 8 + warp;
    if (n >= Nn) return;
    long long base = (long long)n * 128 + lane * 4;
    float r0 = 0.f, r1 = 0.f, r2 = 0.f, r3 = 0.f;
#pragma unroll
    for (int kk = 0; kk < 3; kk++) {
        const float4 f = *(const float4*)&g_front[kk * ND + base];
        const float4 t4 = *(const float4*)&g_tail[kk * ND + base];
        float p = f.x * t4.x + f.y * t4.y + f.z * t4.z + f.w * t4.w;
#pragma unroll
        for (int o = 16; o > 0; o >>= 1) p += __shfl_xor_sync(0xffffffffu, p, o);
        float tt = sigmoidf_(p);
        const float4 am = *(const float4*)&g_aggm[kk * ND + base];
        r0 = fmaf(tt, am.x, r0);
        r1 = fmaf(tt, am.y, r1);
        r2 = fmaf(tt, am.z, r2);
        r3 = fmaf(tt, am.w, r3);
    }
    float4 o;
    o.x = 0.5f * r0 * (1.0f + erff(r0 * 0.70710678118654752f));
    o.y = 0.5f * r1 * (1.0f + erff(r1 * 0.70710678118654752f));
    o.z = 0.5f * r2 * (1.0f + erff(r2 * 0.70710678118654752f));
    o.w = 0.5f * r3 * (1.0f + erff(r3 * 0.70710678118654752f));
    *(float4*)&g_hbuf[base] = o;
}

// ---------------- skip-mix + per-type LayerNorm -----------------------------
__global__ void __launch_bounds__(256) k_final(
    const float* __restrict__ meta, const int* __restrict__ node_type,
    const float* __restrict__ skip, const float* __restrict__ ln_g,
    const float* __restrict__ ln_b, float* __restrict__ out)
{
    int warp = threadIdx.x >> 5, lane = threadIdx.x & 31;
    int n = blockIdx.x * 8 + warp;
    if (n >= Nn) return;
    int t = node_type[n];
    float alpha = sigmoidf_(skip[t]);
    long long base = (long long)n * 128 + lane * 4;
    const float4 tr = *(const float4*)&g_trans[base];
    const float4 x = *(const float4*)&meta[base];
    float y0 = tr.x * alpha + x.x * (1.0f - alpha);
    float y1 = tr.y * alpha + x.y * (1.0f - alpha);
    float y2 = tr.z * alpha + x.z * (1.0f - alpha);
    float y3 = tr.w * alpha + x.w * (1.0f - alpha);
    float s = y0 + y1 + y2 + y3;
    float sq = y0 * y0 + y1 * y1 + y2 * y2 + y3 * y3;
#pragma unroll
    for (int o = 16; o > 0; o >>= 1) {
        s += __shfl_xor_sync(0xffffffffu, s, o);
        sq += __shfl_xor_sync(0xffffffffu, sq, o);
    }
    float mu = s * (1.0f / 128.0f);
    float var = sq * (1.0f / 128.0f) - mu * mu;
    float inv = 1.0f / sqrtf(var + 1e-5f);
    int c = lane * 4;
    const float4 g = *(const float4*)&ln_g[t * 128 + c];
    const float4 b = *(const float4*)&ln_b[t * 128 + c];
    float4 o;
    o.x = (y0 - mu) * inv * g.x + b.x;
    o.y = (y1 - mu) * inv * g.y + b.y;
    o.z = (y2 - mu) * inv * g.z + b.z;
    o.w = (y3 - mu) * inv * g.w + b.w;
    *(float4*)&out[base] = o;
}

// ---------------- host launcher ---------------------------------------------
extern "C" void kernel_launch(void* const* d_in, const int* in_sizes, int n_in,
                              void* d_out, int out_size)
{
    const float* meta      = (const float*)d_in[0];
    const int*   node_type = (const int*)d_in[1];
    const int*   ei        = (const int*)d_in[2];
    const int*   etype     = (const int*)d_in[3];
    const float* q_w = (const float*)d_in[5];
    const float* q_b = (const float*)d_in[6];
    const float* k_w = (const float*)d_in[7];
    const float* k_b = (const float*)d_in[8];
    const float* v_w = (const float*)d_in[9];
    const float* v_b = (const float*)d_in[10];
    const float* a_w = (const float*)d_in[11];
    const float* a_b = (const float*)d_in[12];
    const float* rel_pri = (const float*)d_in[13];
    const float* rel_att = (const float*)d_in[14];
    const float* rel_msg = (const float*)d_in[15];
    const float* WMk = (const float*)d_in[16];
    const float* Wak = (const float*)d_in[17];
    const float* Wq  = (const float*)d_in[18];
    const float* bq  = (const float*)d_in[19];
    const float* Wkl = (const float*)d_in[20];
    const float* bkl = (const float*)d_in[21];
    const float* skip = (const float*)d_in[22];
    const float* ln_g = (const float*)d_in[23];
    const float* ln_b = (const float*)d_in[24];
    float* out = (float*)d_out;

    float *p_qn, *p_kn, *p_vn, *p_agg, *p_aggm, *p_front, *p_tail, *p_hbuf, *p_trans,
          *p_wcomb, *p_bfront;
    cudaGetSymbolAddress((void**)&p_qn, g_qn);
    cudaGetSymbolAddress((void**)&p_kn, g_kn);
    cudaGetSymbolAddress((void**)&p_vn, g_vn);
    cudaGetSymbolAddress((void**)&p_agg, g_agg);
    cudaGetSymbolAddress((void**)&p_aggm, g_aggm);
    cudaGetSymbolAddress((void**)&p_front, g_front);
    cudaGetSymbolAddress((void**)&p_tail, g_tail);
    cudaGetSymbolAddress((void**)&p_hbuf, g_hbuf);
    cudaGetSymbolAddress((void**)&p_trans, g_trans);
    cudaGetSymbolAddress((void**)&p_wcomb, g_wcomb);
    cudaGetSymbolAddress((void**)&p_bfront, g_bfront);

    const int SMEM_EDGE = (RELF + 8 * 128) * 4;               // 86016 B
    const int SMEM_TRANS = (128 * 132 + 32 * 132) * 4;        // 84480 B
    cudaFuncSetAttribute(k_msg, cudaFuncAttributeMaxDynamicSharedMemorySize, SMEM_EDGE);
    cudaFuncSetAttribute(k_rel_transform, cudaFuncAttributeMaxDynamicSharedMemorySize, SMEM_TRANS);

    dim3 blk(256);
    const int GB = 313;   // ceil(40000/128)

    k_init<<<625, blk>>>();
    k_count<<<1250, blk>>>(node_type, ei);
    k_scan<<<1, 32>>>();
    k_scatter<<<157, blk>>>(node_type);

    // typed q/k/v projections
    k_typed_gemm2<<<dim3(GB, 3, 1), blk>>>(meta, q_w, q_b, p_qn);
    k_typed_gemm2<<<dim3(GB, 3, 1), blk>>>(meta, k_w, k_b, p_kn);
    k_typed_gemm2<<<dim3(GB, 3, 1), blk>>>(meta, v_w, v_b, p_vn);

    // fold qlin: Wcomb[k] = Wq @ Wak[k]; bfront[k] = bq @ Wak[k]
    k_gemm2<<<dim3(1, 1, 3), blk>>>(Wq, 0, Wak, 16384, nullptr, 0, p_wcomb, 16384, 128);
    k_bfront<<<3, 128>>>(Wak, bq);

    // knr = kn * rel_att (block-diag per head)
    k_rel_transform<<<dim3(GB, 5, 1), blk, SMEM_TRANS>>>(rel_att);

    // logits + segment max; exp + denominators
    k_logits<<<1184, blk>>>(ei, etype, rel_pri);
    k_expden<<<5000, blk>>>(ei);

    // messages for edge ids < N (reference aggregate quirk: deg * msg[n])
    k_msg<<<296, blk, SMEM_EDGE>>>(ei, etype, rel_msg);

    // aggm[k] = agg[k] @ WMk[k]
    k_gemm2<<<dim3(GB, 1, 3), blk>>>(p_agg, ND, WMk, 16384, nullptr, 0, p_aggm, ND, Nn);
    // front[k] = meta @ Wcomb[k] + bfront[k]
    k_gemm2<<<dim3(GB, 1, 3), blk>>>(meta, 0, p_wcomb, 16384, p_bfront, 128, p_front, ND, Nn);
    // tail[k] = aggm[k] @ Wkl + bkl
    k_gemm2<<<dim3(GB, 1, 3), blk>>>(p_aggm, ND, Wkl, 0, bkl, 0, p_tail, ND, Nn);

    k_res<<<5000, blk>>>();

    k_typed_gemm2<<<dim3(GB, 3, 1), blk>>>(p_hbuf, a_w, a_b, p_trans);

    k_final<<<5000, blk>>>(meta, node_type, skip, ln_g, ln_b, out);
}